// round 2
// baseline (speedup 1.0000x reference)
#include <cuda_runtime.h>

#define BATCH 64
#define FEAT  784
#define DIM   1001
#define DIMSQ (DIM * DIM)          // 1002001
#define PAD   1008                 // padded state length (mult of 16B, covers shifts)
#define ROWS_PER_CTA 56
#define CTAS_X 18                  // 18 * 56 = 1008 >= 1001 rows

// Single fused kernel:
//  - each CTA owns (batch b, rows [i0, i0+56))
//  - computes the batch norm itself (784 loads, amortized over 224KB of stores)
//  - builds 4 shifted+scaled+zero-padded copies of the state in smem so every
//    output float4 is one conflict-free LDS.128, regardless of row alignment
//  - streams out[b,i,j] = s_i * s_j with STG.128 only
__global__ void __launch_bounds__(256) amp_outer_kernel(const float* __restrict__ x,
                                                        float* __restrict__ out) {
    __shared__ float raw[PAD];
    __shared__ float s_sh[4][PAD];   // s_sh[a][m] = state[a+m] (0 beyond FEAT)
    __shared__ float red[8];
    __shared__ float s_inv;

    const int b   = blockIdx.y;
    const int tid = threadIdx.x;

    // ---- load raw features (zero-padded) ----
    const float* xb = x + b * FEAT;
    for (int idx = tid; idx < PAD; idx += 256)
        raw[idx] = (idx < FEAT) ? xb[idx] : 0.0f;
    __syncthreads();

    // ---- block reduce: sum of squares -> inv norm ----
    float p = 0.0f;
    for (int idx = tid; idx < PAD; idx += 256) {
        float v = raw[idx];
        p += v * v;
    }
    #pragma unroll
    for (int o = 16; o > 0; o >>= 1)
        p += __shfl_xor_sync(0xFFFFFFFFu, p, o);
    if ((tid & 31) == 0) red[tid >> 5] = p;
    __syncthreads();
    if (tid == 0) {
        float s = 0.0f;
        #pragma unroll
        for (int i = 0; i < 8; i++) s += red[i];
        s_inv = rsqrtf(s);
    }
    __syncthreads();
    const float inv = s_inv;

    // ---- build 4 shifted, scaled, zero-padded copies ----
    for (int idx = tid; idx < 4 * PAD; idx += 256) {
        const int a   = idx / PAD;          // compile-time const div
        const int m   = idx - a * PAD;
        const int src = a + m;
        s_sh[a][m] = (src < FEAT) ? raw[src] * inv : 0.0f;
    }
    __syncthreads();

    // ---- stream the rows ----
    const int i0    = blockIdx.x * ROWS_PER_CTA;
    const int i_end = (i0 + ROWS_PER_CTA < DIM) ? i0 + ROWS_PER_CTA : DIM;

    for (int i = i0; i < i_end; ++i) {
        const float si = s_sh[0][i];                 // broadcast LDS; 0 for i>=784
        const int   o  = b * DIMSQ + i * DIM;        // row start (element index)
        const int   h  = (4 - (o & 3)) & 3;          // scalar head to reach 16B align
        const int   nq = (DIM - h) >> 2;             // aligned quads in this row (<=250)

        if (tid < nq) {
            // elements j = h+4t .. h+4t+3  ==  s_sh[h][4t .. 4t+3]
            const float4 sv = *reinterpret_cast<const float4*>(&s_sh[h][4 * tid]);
            float4 r;
            r.x = si * sv.x;
            r.y = si * sv.y;
            r.z = si * sv.z;
            r.w = si * sv.w;
            *reinterpret_cast<float4*>(out + o + h + 4 * tid) = r;
        } else {
            // leftover threads cover head [0,h) and tail [h+4nq, DIM)
            const int k     = tid - nq;
            const int nscal = DIM - 4 * nq;          // h + tail count (<=5)
            if (k < nscal) {
                const int j = (k < h) ? k : (4 * nq + k);
                out[o + j] = si * s_sh[0][j];
            }
        }
    }
}

extern "C" void kernel_launch(void* const* d_in, const int* in_sizes, int n_in,
                              void* d_out, int out_size) {
    const float* x   = (const float*)d_in[0];
    float*       out = (float*)d_out;
    amp_outer_kernel<<<dim3(CTAS_X, BATCH), 256>>>(x, out);
}

// round 3
// speedup vs baseline: 1.1781x; 1.1781x over previous
#include <cuda_runtime.h>

#define BATCH 64
#define FEAT  784
#define DIM   1001
#define DIMSQ (DIM * DIM)          // 1002001
#define PADS  1008                 // padded shifted-state length (>= 1004, mult of 4)

// Scratch: 4 shifted, scaled, zero-padded copies of each batch's state.
// g_shift[b][a][m] = (a+m < FEAT) ? state_b[a+m] : 0
__device__ float g_shift[BATCH][4][PADS];   // ~1 MB, L2-resident

// ---------------------------------------------------------------------------
// Kernel 1: per-batch norm + write the 4 shifted copies. 64 CTAs, tiny.
// ---------------------------------------------------------------------------
__global__ void __launch_bounds__(256) norm_shift_kernel(const float* __restrict__ x) {
    __shared__ float raw[FEAT];
    __shared__ float red[8];
    __shared__ float s_inv;

    const int b   = blockIdx.x;
    const int tid = threadIdx.x;
    const float* xb = x + b * FEAT;

    float p = 0.0f;
    for (int j = tid; j < FEAT; j += 256) {
        float v = xb[j];
        raw[j] = v;
        p += v * v;
    }
    #pragma unroll
    for (int o = 16; o > 0; o >>= 1)
        p += __shfl_xor_sync(0xFFFFFFFFu, p, o);
    if ((tid & 31) == 0) red[tid >> 5] = p;
    __syncthreads();
    if (tid == 0) {
        float s = 0.0f;
        #pragma unroll
        for (int i = 0; i < 8; i++) s += red[i];
        s_inv = rsqrtf(s);
    }
    __syncthreads();
    const float inv = s_inv;

    for (int idx = tid; idx < 4 * PADS; idx += 256) {
        const int a   = idx / PADS;         // const div
        const int m   = idx - a * PADS;
        const int src = a + m;
        g_shift[b][a][m] = (src < FEAT) ? raw[src] * inv : 0.0f;
    }
}

// ---------------------------------------------------------------------------
// Kernel 2: flat float4 grid-stride outer product.
// Per quad: 1 broadcast LDG (si) + 1 coalesced LDG.128 (sj) + 1 STG.128.
// ---------------------------------------------------------------------------
__global__ void __launch_bounds__(256) outer_kernel(float4* __restrict__ out,
                                                    unsigned n4) {
    const unsigned stride = gridDim.x * blockDim.x;
    for (unsigned q = blockIdx.x * blockDim.x + threadIdx.x; q < n4; q += stride) {
        const unsigned e   = q * 4u;
        const unsigned b   = e / (unsigned)DIMSQ;
        const unsigned rem = e - b * (unsigned)DIMSQ;
        const unsigned i   = rem / (unsigned)DIM;
        const unsigned j   = rem - i * (unsigned)DIM;

        float4 r;
        if (j + 3u < (unsigned)DIM) {
            // Quad fully inside one row (~99.6%). Zero-padding handles i,j >= FEAT.
            const float    si = g_shift[b][0][i];
            const unsigned a  = j & 3u;
            const unsigned t  = j - a;                         // multiple of 4
            const float4   sv = *reinterpret_cast<const float4*>(&g_shift[b][a][t]);
            r.x = si * sv.x;
            r.y = si * sv.y;
            r.z = si * sv.z;
            r.w = si * sv.w;
        } else {
            // Row/batch straddle (~0.4%): per-lane math, still one STG.128.
            float vals[4];
            #pragma unroll
            for (int k = 0; k < 4; k++) {
                const unsigned ee = e + (unsigned)k;
                const unsigned bb = ee / (unsigned)DIMSQ;
                const unsigned r2 = ee - bb * (unsigned)DIMSQ;
                const unsigned ii = r2 / (unsigned)DIM;
                const unsigned jj = r2 - ii * (unsigned)DIM;
                vals[k] = g_shift[bb][0][ii] * g_shift[bb][0][jj];
            }
            r = make_float4(vals[0], vals[1], vals[2], vals[3]);
        }
        out[q] = r;
    }
}

// ---------------------------------------------------------------------------
extern "C" void kernel_launch(void* const* d_in, const int* in_sizes, int n_in,
                              void* d_out, int out_size) {
    const float* x   = (const float*)d_in[0];
    float*       out = (float*)d_out;

    norm_shift_kernel<<<BATCH, 256>>>(x);

    const unsigned n4 = (unsigned)(out_size / 4);   // 16,032,016
    outer_kernel<<<1184, 256>>>((float4*)out, n4);  // single full wave
}

// round 4
// speedup vs baseline: 1.2584x; 1.0682x over previous
#include <cuda_runtime.h>

#define BATCH 64
#define FEAT  784
#define DIM   1001
#define DIMSQ (DIM * DIM)        // 1002001
#define ROWS_PER_CTA 14
#define CTAS_X 72                // 72*14 = 1008 >= 1001 rows

// Single fused kernel. CTA = (row-chunk cx, batch b), 128 threads.
// Thread t holds 16 state values in registers:
//   w0[0..7]  = s[4t   .. 4t+8)
//   w1[0..7]  = s[512+4t .. 512+4t+8)
// Row i's aligned quads start at j === a (mod 4), a = (-(b+i)) mod 4.
// Pass0 quad j = a+4t  (slice w0[a..a+3]); pass1 quad j = a+512+4t (w1[a..a+3]).
__global__ void __launch_bounds__(128) amp_kernel(const float* __restrict__ x,
                                                  float* __restrict__ out) {
    __shared__ float s_sm[1032];          // scaled state, zero-padded
    __shared__ float red[4];
    __shared__ float s_inv;

    const int tid = threadIdx.x;
    const int b   = blockIdx.y;
    const float* xb = x + b * FEAT;

    // ---- norm (redundant per CTA; x is L2-resident) ----
    float p = 0.0f;
    for (int j = tid; j < FEAT; j += 128) { float v = xb[j]; p += v * v; }
    #pragma unroll
    for (int o = 16; o > 0; o >>= 1) p += __shfl_xor_sync(0xFFFFFFFFu, p, o);
    if ((tid & 31) == 0) red[tid >> 5] = p;
    __syncthreads();
    if (tid == 0) s_inv = rsqrtf(red[0] + red[1] + red[2] + red[3]);
    __syncthreads();
    const float inv = s_inv;

    for (int j = tid; j < 1032; j += 128)
        s_sm[j] = (j < FEAT) ? xb[j] * inv : 0.0f;
    __syncthreads();

    // ---- register windows ----
    float w0[8], w1[8];
    {
        const float4 a0 = *reinterpret_cast<const float4*>(&s_sm[4 * tid]);
        const float4 a1 = *reinterpret_cast<const float4*>(&s_sm[4 * tid + 4]);
        const float4 b0 = *reinterpret_cast<const float4*>(&s_sm[512 + 4 * tid]);
        const float4 b1 = *reinterpret_cast<const float4*>(&s_sm[512 + 4 * tid + 4]);
        w0[0]=a0.x; w0[1]=a0.y; w0[2]=a0.z; w0[3]=a0.w;
        w0[4]=a1.x; w0[5]=a1.y; w0[6]=a1.z; w0[7]=a1.w;
        w1[0]=b0.x; w1[1]=b0.y; w1[2]=b0.z; w1[3]=b0.w;
        w1[4]=b1.x; w1[5]=b1.y; w1[6]=b1.z; w1[7]=b1.w;
    }

    // ---- stream rows ----
    const int i0   = blockIdx.x * ROWS_PER_CTA;
    const int iend = (i0 + ROWS_PER_CTA < DIM) ? (i0 + ROWS_PER_CTA) : DIM;

    for (int i = i0; i < iend; ++i) {
        const float si   = s_sm[i];                       // broadcast LDS (0 for i>=784)
        float* rowp      = out + (size_t)b * DIMSQ + (size_t)i * DIM;
        const int a      = (4 - ((b + i) & 3)) & 3;       // aligned-quad phase

        // head scalars j in [0, a)
        if (tid < a) rowp[tid] = si * s_sm[tid];
        // tail scalars j in [ts, 1001): always j >= 998 >= FEAT -> zero
        const int ts = 998 + ((a + 2) & 3);               // a=0:1000 1:1001 2:998 3:999
        if (tid >= 8 && tid < 8 + (DIM - ts)) rowp[ts + tid - 8] = 0.0f;

        // main quads: static slice per phase
        float4 v0, v1;
        switch (a) {
            case 0: v0 = make_float4(w0[0], w0[1], w0[2], w0[3]);
                    v1 = make_float4(w1[0], w1[1], w1[2], w1[3]); break;
            case 1: v0 = make_float4(w0[1], w0[2], w0[3], w0[4]);
                    v1 = make_float4(w1[1], w1[2], w1[3], w1[4]); break;
            case 2: v0 = make_float4(w0[2], w0[3], w0[4], w0[5]);
                    v1 = make_float4(w1[2], w1[3], w1[4], w1[5]); break;
            default: v0 = make_float4(w0[3], w0[4], w0[5], w0[6]);
                     v1 = make_float4(w1[3], w1[4], w1[5], w1[6]); break;
        }
        v0.x *= si; v0.y *= si; v0.z *= si; v0.w *= si;
        v1.x *= si; v1.y *= si; v1.z *= si; v1.w *= si;

        const int j0 = a + 4 * tid;                       // <= 511, always valid
        __stcs(reinterpret_cast<float4*>(rowp + j0), v0);
        const int j1 = j0 + 512;
        if (j1 <= DIM - 4)                                 // quad fully in row
            __stcs(reinterpret_cast<float4*>(rowp + j1), v1);
    }
}

extern "C" void kernel_launch(void* const* d_in, const int* in_sizes, int n_in,
                              void* d_out, int out_size) {
    const float* x   = (const float*)d_in[0];
    float*       out = (float*)d_out;
    amp_kernel<<<dim3(CTAS_X, BATCH), 128>>>(x, out);
}